// round 2
// baseline (speedup 1.0000x reference)
#include <cuda_runtime.h>
#include <cuda_bf16.h>
#include <cstdint>

// Problem constants
#define Hn 1024
#define Bn 128
#define Tn 400
#define Sn 64
#define Cn 8
#define NOUTn 3
#define NCLSn 3
#define BOTn 2
#define CLSOUTn 8
#define NEXC 819              // int(1024 * 0.8)

#define NCTA 128              // CTAs in scan kernel (one j-slice each)
#define JPC 8                 // hidden columns per CTA (128 * 8 = 1024)

#define ALPHA_N 0.2f          // DT/TAU_N = 20/100
#define DT_SEC 0.02f
#define NOISE_STD 0.05f
#define AX_SLOW ((float)(20.0 / 1500.0))
#define AX_FAST ((float)(20.0 / 200.0))

#define NR (NOUTn + NCLSn * CLSOUTn)   // 27 fused readout rows

// ---------------- device scratch (no cudaMalloc allowed) ----------------
__device__ float g_drive[(size_t)Tn * Bn * Hn];   // [t][b][h]  (~210 MB)
__device__ float g_hpT[2][Hn * Bn];               // transposed h_post, double buffered
__device__ float g_winT[Sn * Hn];                 // w_in transposed [s][h]
__device__ float g_wctxT[Cn * Hn];                // w_ctx transposed [c][h]
__device__ float g_comb[NR * Hn];                 // fused readout weights (w_out + c2@c1)
__device__ float g_combb[NR];                     // fused biases
__device__ unsigned g_count;                      // barrier arrival counter
__device__ volatile unsigned g_phase;             // barrier phase

// ---------------- prep: reset barrier, transpose weights, fuse classifiers ----
__global__ void prep_kernel(const float* __restrict__ w_in,
                            const float* __restrict__ w_ctx,
                            const float* __restrict__ w_out,
                            const float* __restrict__ b_out,
                            const float* __restrict__ c1_w,
                            const float* __restrict__ c1_b,
                            const float* __restrict__ c2_w,
                            const float* __restrict__ c2_b) {
    int idx = blockIdx.x * blockDim.x + threadIdx.x;
    if (idx == 0) { g_count = 0; g_phase = 0; }

    if (idx < Hn * Sn) {                      // transpose w_in [H,S] -> [S,H]
        int h = idx / Sn, s = idx % Sn;
        g_winT[s * Hn + h] = w_in[idx];
    }
    if (idx < Hn * Cn) {                      // transpose w_ctx [H,C] -> [C,H]
        int h = idx / Cn, c = idx % Cn;
        g_wctxT[c * Hn + h] = w_ctx[idx];
    }
    if (idx < NOUTn * Hn) {                   // rows 0..2 : w_out
        g_comb[idx] = w_out[idx];
    }
    if (idx < NCLSn * CLSOUTn * Hn) {         // rows 3..26 : c2_w @ c1_w
        int r = idx / Hn, h = idx % Hn;
        int j = r / CLSOUTn, o = r % CLSOUTn;
        float acc = 0.f;
        #pragma unroll
        for (int k = 0; k < BOTn; k++)
            acc += c2_w[(j * CLSOUTn + o) * BOTn + k] * c1_w[(j * BOTn + k) * Hn + h];
        g_comb[(NOUTn + r) * Hn + h] = acc;
    }
    if (idx < NOUTn) g_combb[idx] = b_out[idx];
    if (idx >= NOUTn && idx < NR) {
        int r = idx - NOUTn;
        int j = r / CLSOUTn, o = r % CLSOUTn;
        float acc = c2_b[j * CLSOUTn + o];
        #pragma unroll
        for (int k = 0; k < BOTn; k++)
            acc += c2_w[(j * CLSOUTn + o) * BOTn + k] * c1_b[j * BOTn + k];
        g_combb[idx] = acc;
    }
}

// ---------------- drive: [t][b][h] = stim@w_in^T + ctx@w_ctx^T ----------------
#define DG 8   // (t,b) pairs per block
__global__ void drive_kernel(const float* __restrict__ stim,
                             const float* __restrict__ ctx) {
    __shared__ float s_in[DG][Sn + Cn];
    int p0 = blockIdx.x * DG;                         // pair index p = t*B + b
    int h = blockIdx.y * blockDim.x + threadIdx.x;

    for (int i = threadIdx.x; i < DG * (Sn + Cn); i += blockDim.x) {
        int g = i / (Sn + Cn), q = i % (Sn + Cn);
        int p = p0 + g;
        int t = p / Bn, b = p % Bn;
        float v;
        if (q < Sn) v = stim[((size_t)b * Tn + t) * Sn + q];
        else        v = ctx[((size_t)b * Tn + t) * Cn + (q - Sn)];
        s_in[g][q] = v;
    }
    __syncthreads();

    float acc[DG];
    #pragma unroll
    for (int g = 0; g < DG; g++) acc[g] = 0.f;

    #pragma unroll 8
    for (int s = 0; s < Sn; s++) {
        float w = g_winT[s * Hn + h];
        #pragma unroll
        for (int g = 0; g < DG; g++) acc[g] = fmaf(s_in[g][s], w, acc[g]);
    }
    #pragma unroll
    for (int c = 0; c < Cn; c++) {
        float w = g_wctxT[c * Hn + h];
        #pragma unroll
        for (int g = 0; g < DG; g++) acc[g] = fmaf(s_in[g][Sn + c], w, acc[g]);
    }
    #pragma unroll
    for (int g = 0; g < DG; g++)
        g_drive[(size_t)(p0 + g) * Hn + h] = acc[g];
}

// ---------------- persistent scan kernel ----------------
__global__ void __launch_bounds__(Bn, 1) scan_kernel(
        const float* __restrict__ w_rec,
        const float* __restrict__ b_rec,
        const float* __restrict__ noise,
        float* __restrict__ acts) {
    __shared__ float w_sm[Hn * JPC];   // W_eff[k][jj] for this CTA's j-slice (32 KB)
    const int c = blockIdx.x;
    const int b = threadIdx.x;         // one batch row per thread
    const int j0 = c * JPC;

    // Build effective recurrent weights for owned columns: sign * relu * no-diag
    for (int idx = b; idx < Hn * JPC; idx += Bn) {
        int k = idx / JPC, jj = idx % JPC;
        int j = j0 + jj;
        float w = fmaxf(w_rec[(size_t)k * Hn + j], 0.f);
        if (k == j) w = 0.f;
        w_sm[idx] = (k < NEXC) ? w : -w;
    }
    float br[JPC];
    #pragma unroll
    for (int jj = 0; jj < JPC; jj++) br[jj] = b_rec[j0 + jj];
    __syncthreads();

    // State in registers
    float h[JPC], sx[JPC], su[JPC], Uv[JPC], ax[JPC];
    #pragma unroll
    for (int jj = 0; jj < JPC; jj++) {
        int j = j0 + jj;
        bool odd = (j & 1);
        ax[jj] = odd ? AX_FAST : AX_SLOW;
        Uv[jj] = odd ? 0.15f : 0.45f;
        h[jj] = 0.f;
        sx[jj] = 1.f;
        su[jj] = Uv[jj];
    }

    for (int step = 0; step < Tn; step++) {
        float* hpT = g_hpT[step & 1];

        // ---- STP update + write transposed h_post ----
        #pragma unroll
        for (int jj = 0; jj < JPC; jj++) {
            float hh = h[jj];
            float sxo = sx[jj], suo = su[jj];
            float sxn = sxo + ax[jj] * (1.f - sxo) - DT_SEC * suo * sxo * hh;
            float sun = suo + ax[jj] * (Uv[jj] - suo) + DT_SEC * Uv[jj] * (1.f - suo) * hh;
            sxn = fminf(fmaxf(sxn, 0.f), 1.f);
            sun = fminf(fmaxf(sun, 0.f), 1.f);
            sx[jj] = sxn;
            su[jj] = sun;
            hpT[(j0 + jj) * Bn + b] = sun * sxn * hh;
        }

        // ---- grid barrier (monotonic phase, one per step) ----
        __threadfence();
        __syncthreads();
        if (b == 0) {
            unsigned target = (unsigned)(step + 1);
            unsigned v = atomicAdd(&g_count, 1u);
            if (v == target * NCTA - 1u) {
                __threadfence();
                g_phase = target;
            } else {
                while (g_phase < target) { }
            }
            __threadfence();
        }
        __syncthreads();

        // ---- GEMM: acc[jj] = sum_k hpT[k][b] * W[k][j0+jj] ----
        float acc[JPC];
        #pragma unroll
        for (int jj = 0; jj < JPC; jj++) acc[jj] = 0.f;

        const float* __restrict__ hpcol = hpT + b;
        float hvA[32], hvB[32];
        #pragma unroll
        for (int u = 0; u < 32; u++) hvA[u] = hpcol[u * Bn];

        for (int kb = 0; kb < Hn; kb += 64) {
            // prefetch second half of this 64-block
            #pragma unroll
            for (int u = 0; u < 32; u++) hvB[u] = hpcol[(kb + 32 + u) * Bn];
            // compute first half
            #pragma unroll
            for (int u = 0; u < 32; u++) {
                const float* wr = &w_sm[(kb + u) * JPC];
                #pragma unroll
                for (int jj = 0; jj < JPC; jj++)
                    acc[jj] = fmaf(hvA[u], wr[jj], acc[jj]);
            }
            // prefetch first half of next 64-block
            if (kb + 64 < Hn) {
                #pragma unroll
                for (int u = 0; u < 32; u++) hvA[u] = hpcol[(kb + 64 + u) * Bn];
            }
            // compute second half
            #pragma unroll
            for (int u = 0; u < 32; u++) {
                const float* wr = &w_sm[(kb + 32 + u) * JPC];
                #pragma unroll
                for (int jj = 0; jj < JPC; jj++)
                    acc[jj] = fmaf(hvB[u], wr[jj], acc[jj]);
            }
        }

        // ---- h update + write acts ----
        const size_t off = ((size_t)step * Bn + b) * Hn + j0;
        const float* __restrict__ drv = g_drive + off;
        const float* __restrict__ nz  = noise + off;
        float* __restrict__ ao = acts + ((size_t)b * Tn + step) * Hn + j0;
        #pragma unroll
        for (int jj = 0; jj < JPC; jj++) {
            float val = h[jj] * (1.f - ALPHA_N)
                      + ALPHA_N * (drv[jj] + acc[jj] + br[jj])
                      + NOISE_STD * nz[jj];
            float hn = fmaxf(val, 0.f);
            h[jj] = hn;
            ao[jj] = hn;
        }
    }
}

// ---------------- post: fused readout (outputs + classifier logits) ----------------
__global__ void post_kernel(const float* __restrict__ acts,
                            float* __restrict__ out0,
                            float* __restrict__ pout) {
    __shared__ float s_a[Hn];
    __shared__ float s_red[8][NR];
    int bt = blockIdx.x;                     // bt = b*T + t
    const float* arow = acts + (size_t)bt * Hn;
    int tid = threadIdx.x;                   // 256 threads

    for (int i = tid; i < Hn; i += 256) s_a[i] = arow[i];
    __syncthreads();

    float part[NR];
    #pragma unroll
    for (int r = 0; r < NR; r++) part[r] = 0.f;

    for (int i = tid; i < Hn; i += 256) {
        float a = s_a[i];
        #pragma unroll
        for (int r = 0; r < NR; r++)
            part[r] = fmaf(a, g_comb[r * Hn + i], part[r]);
    }
    #pragma unroll
    for (int r = 0; r < NR; r++) {
        #pragma unroll
        for (int off = 16; off > 0; off >>= 1)
            part[r] += __shfl_down_sync(0xffffffffu, part[r], off);
    }
    int wid = tid >> 5, lid = tid & 31;
    if (lid == 0) {
        #pragma unroll
        for (int r = 0; r < NR; r++) s_red[wid][r] = part[r];
    }
    __syncthreads();
    if (tid < NR) {
        float s = 0.f;
        #pragma unroll
        for (int w = 0; w < 8; w++) s += s_red[w][tid];
        s += g_combb[tid];
        if (tid < NOUTn) out0[(size_t)bt * NOUTn + tid] = s;
        else             pout[(size_t)bt * (NCLSn * CLSOUTn) + (tid - NOUTn)] = s;
    }
}

// ---------------- launch ----------------
extern "C" void kernel_launch(void* const* d_in, const int* in_sizes, int n_in,
                              void* d_out, int out_size) {
    const float* stim  = (const float*)d_in[0];
    const float* ctx   = (const float*)d_in[1];
    const float* w_rec = (const float*)d_in[2];
    const float* b_rec = (const float*)d_in[3];
    const float* w_in  = (const float*)d_in[4];
    const float* w_ctx = (const float*)d_in[5];
    const float* w_out = (const float*)d_in[6];
    const float* b_out = (const float*)d_in[7];
    const float* c1_w  = (const float*)d_in[8];
    const float* c1_b  = (const float*)d_in[9];
    const float* c2_w  = (const float*)d_in[10];
    const float* c2_b  = (const float*)d_in[11];
    const float* noise = (const float*)d_in[12];

    float* out0 = (float*)d_out;                         // [B, T, 3]
    float* acts = out0 + (size_t)Bn * Tn * NOUTn;        // [B, T, H]
    float* pout = acts + (size_t)Bn * Tn * Hn;           // [B, T, 3, 8]

    prep_kernel<<<256, 256>>>(w_in, w_ctx, w_out, b_out, c1_w, c1_b, c2_w, c2_b);

    dim3 dgrid(Tn * Bn / DG, Hn / 256);
    drive_kernel<<<dgrid, 256>>>(stim, ctx);

    scan_kernel<<<NCTA, Bn>>>(w_rec, b_rec, noise, acts);

    post_kernel<<<Bn * Tn, 256>>>(acts, out0, pout);
}

// round 3
// speedup vs baseline: 1.0691x; 1.0691x over previous
#include <cuda_runtime.h>
#include <cuda_bf16.h>
#include <cstdint>

// Problem constants
#define Hn 1024
#define Bn 128
#define Tn 400
#define Sn 64
#define Cn 8
#define NOUTn 3
#define NCLSn 3
#define BOTn 2
#define CLSOUTn 8
#define NEXC 819              // int(1024 * 0.8)

#define NCTA 128              // CTAs in scan kernel (one j-slice each)
#define JPC 8                 // hidden columns per CTA

#define ALPHA_N 0.2f          // DT/TAU_N = 20/100
#define DT_SEC 0.02f
#define NOISE_STD 0.05f
#define NZ_SCALE 0.25f        // NOISE_STD / ALPHA_N
#define AX_SLOW ((float)(20.0 / 1500.0))
#define AX_FAST ((float)(20.0 / 200.0))

#define NR (NOUTn + NCLSn * CLSOUTn)   // 27 fused readout rows

// ---------------- device scratch ----------------
__device__ float g_drive[(size_t)Tn * Hn * Bn];   // [t][h][b], noise folded in
__device__ float g_hpT[2][Hn * Bn];               // transposed h_post (float4-packed rows)
__device__ float g_comb[NR * Hn];                 // fused readout weights
__device__ float g_combb[NR];                     // fused biases
__device__ unsigned g_count;                      // barrier arrival counter
__device__ volatile unsigned g_phase;             // barrier phase

// ---------------- packed f32x2 helpers ----------------
__device__ __forceinline__ unsigned long long fma2(unsigned long long a,
                                                   unsigned long long b,
                                                   unsigned long long c) {
    unsigned long long d;
    asm("fma.rn.f32x2 %0, %1, %2, %3;" : "=l"(d) : "l"(a), "l"(b), "l"(c));
    return d;
}
__device__ __forceinline__ unsigned long long pack2(float v) {
    unsigned long long d;
    unsigned r = __float_as_uint(v);
    asm("mov.b64 %0, {%1, %2};" : "=l"(d) : "r"(r), "r"(r));
    return d;
}
__device__ __forceinline__ void unpack2(unsigned long long p, float& lo, float& hi) {
    unsigned a, b;
    asm("mov.b64 {%0, %1}, %2;" : "=r"(a), "=r"(b) : "l"(p));
    lo = __uint_as_float(a);
    hi = __uint_as_float(b);
}

// ---------------- prep: reset barrier, fuse classifiers ----------------
__global__ void prep_kernel(const float* __restrict__ w_out,
                            const float* __restrict__ b_out,
                            const float* __restrict__ c1_w,
                            const float* __restrict__ c1_b,
                            const float* __restrict__ c2_w,
                            const float* __restrict__ c2_b) {
    int idx = blockIdx.x * blockDim.x + threadIdx.x;
    if (idx == 0) { g_count = 0; g_phase = 0; }

    if (idx < NOUTn * Hn) {                   // rows 0..2 : w_out
        g_comb[idx] = w_out[idx];
    }
    if (idx < NCLSn * CLSOUTn * Hn) {         // rows 3..26 : c2_w @ c1_w
        int r = idx / Hn, h = idx % Hn;
        int j = r / CLSOUTn, o = r % CLSOUTn;
        float acc = 0.f;
        #pragma unroll
        for (int k = 0; k < BOTn; k++)
            acc += c2_w[(j * CLSOUTn + o) * BOTn + k] * c1_w[(j * BOTn + k) * Hn + h];
        g_comb[(NOUTn + r) * Hn + h] = acc;
    }
    if (idx < NOUTn) g_combb[idx] = b_out[idx];
    if (idx >= NOUTn && idx < NR) {
        int r = idx - NOUTn;
        int j = r / CLSOUTn, o = r % CLSOUTn;
        float acc = c2_b[j * CLSOUTn + o];
        #pragma unroll
        for (int k = 0; k < BOTn; k++)
            acc += c2_w[(j * CLSOUTn + o) * BOTn + k] * c1_b[j * BOTn + k];
        g_combb[idx] = acc;
    }
}

// ---------------- drive: g_drive[t][h][b] = stim@w_in^T + ctx@w_ctx^T + 0.25*noise ----
__global__ void __launch_bounds__(256) drive_kernel(
        const float* __restrict__ stim,
        const float* __restrict__ ctx,
        const float* __restrict__ noise,
        const float* __restrict__ w_in,
        const float* __restrict__ w_ctx) {
    const int t = blockIdx.x;
    const int g = threadIdx.x >> 7;
    const int b = threadIdx.x & 127;
    const int h0 = blockIdx.y * 256 + g * 128;

    // per-thread inputs in registers (fully unrolled indexing)
    float sin_r[Sn], cin_r[Cn];
    const float4* sp = (const float4*)(stim + ((size_t)b * Tn + t) * Sn);
    #pragma unroll
    for (int q = 0; q < Sn / 4; q++) {
        float4 v = sp[q];
        sin_r[4*q] = v.x; sin_r[4*q+1] = v.y; sin_r[4*q+2] = v.z; sin_r[4*q+3] = v.w;
    }
    const float4* cp = (const float4*)(ctx + ((size_t)b * Tn + t) * Cn);
    #pragma unroll
    for (int q = 0; q < Cn / 4; q++) {
        float4 v = cp[q];
        cin_r[4*q] = v.x; cin_r[4*q+1] = v.y; cin_r[4*q+2] = v.z; cin_r[4*q+3] = v.w;
    }
    const float4* nzp = (const float4*)(noise + ((size_t)t * Bn + b) * Hn);

    for (int hh = 0; hh < 128; hh += 4) {
        const int h = h0 + hh;
        float acc0 = 0.f, acc1 = 0.f, acc2 = 0.f, acc3 = 0.f;
        #pragma unroll
        for (int s4 = 0; s4 < Sn / 4; s4++) {
            float4 w0 = *(const float4*)(w_in + (size_t)(h + 0) * Sn + s4 * 4);
            float4 w1 = *(const float4*)(w_in + (size_t)(h + 1) * Sn + s4 * 4);
            float4 w2 = *(const float4*)(w_in + (size_t)(h + 2) * Sn + s4 * 4);
            float4 w3 = *(const float4*)(w_in + (size_t)(h + 3) * Sn + s4 * 4);
            float i0 = sin_r[4*s4], i1 = sin_r[4*s4+1], i2 = sin_r[4*s4+2], i3 = sin_r[4*s4+3];
            acc0 = fmaf(i0, w0.x, acc0); acc0 = fmaf(i1, w0.y, acc0);
            acc0 = fmaf(i2, w0.z, acc0); acc0 = fmaf(i3, w0.w, acc0);
            acc1 = fmaf(i0, w1.x, acc1); acc1 = fmaf(i1, w1.y, acc1);
            acc1 = fmaf(i2, w1.z, acc1); acc1 = fmaf(i3, w1.w, acc1);
            acc2 = fmaf(i0, w2.x, acc2); acc2 = fmaf(i1, w2.y, acc2);
            acc2 = fmaf(i2, w2.z, acc2); acc2 = fmaf(i3, w2.w, acc2);
            acc3 = fmaf(i0, w3.x, acc3); acc3 = fmaf(i1, w3.y, acc3);
            acc3 = fmaf(i2, w3.z, acc3); acc3 = fmaf(i3, w3.w, acc3);
        }
        #pragma unroll
        for (int c4 = 0; c4 < Cn / 4; c4++) {
            float4 w0 = *(const float4*)(w_ctx + (size_t)(h + 0) * Cn + c4 * 4);
            float4 w1 = *(const float4*)(w_ctx + (size_t)(h + 1) * Cn + c4 * 4);
            float4 w2 = *(const float4*)(w_ctx + (size_t)(h + 2) * Cn + c4 * 4);
            float4 w3 = *(const float4*)(w_ctx + (size_t)(h + 3) * Cn + c4 * 4);
            float i0 = cin_r[4*c4], i1 = cin_r[4*c4+1], i2 = cin_r[4*c4+2], i3 = cin_r[4*c4+3];
            acc0 = fmaf(i0, w0.x, acc0); acc0 = fmaf(i1, w0.y, acc0);
            acc0 = fmaf(i2, w0.z, acc0); acc0 = fmaf(i3, w0.w, acc0);
            acc1 = fmaf(i0, w1.x, acc1); acc1 = fmaf(i1, w1.y, acc1);
            acc1 = fmaf(i2, w1.z, acc1); acc1 = fmaf(i3, w1.w, acc1);
            acc2 = fmaf(i0, w2.x, acc2); acc2 = fmaf(i1, w2.y, acc2);
            acc2 = fmaf(i2, w2.z, acc2); acc2 = fmaf(i3, w2.w, acc2);
            acc3 = fmaf(i0, w3.x, acc3); acc3 = fmaf(i1, w3.y, acc3);
            acc3 = fmaf(i2, w3.z, acc3); acc3 = fmaf(i3, w3.w, acc3);
        }
        float4 nz = nzp[h >> 2];
        float* gd = g_drive + ((size_t)t * Hn + h) * Bn + b;
        gd[0]        = fmaf(NZ_SCALE, nz.x, acc0);
        gd[Bn]       = fmaf(NZ_SCALE, nz.y, acc1);
        gd[2 * Bn]   = fmaf(NZ_SCALE, nz.z, acc2);
        gd[3 * Bn]   = fmaf(NZ_SCALE, nz.w, acc3);
    }
}

// ---------------- persistent scan kernel ----------------
__global__ void __launch_bounds__(256, 1) scan_kernel(
        const float* __restrict__ w_rec,
        const float* __restrict__ b_rec,
        float* __restrict__ acts) {
    __shared__ __align__(16) float w_sm[Hn * JPC];   // 32 KB
    const int c   = blockIdx.x;
    const int tid = threadIdx.x;
    const int b   = tid & 127;
    const int g   = tid >> 7;            // 0/1: column half
    const int j0  = c * JPC;
    const int jg  = j0 + g * 4;          // first of this thread's 4 columns

    // Effective recurrent weights: sign * relu * no-diag, layout [k][8]
    for (int idx = tid; idx < Hn * JPC; idx += 256) {
        int k = idx >> 3, jj = idx & 7;
        int j = j0 + jj;
        float w = fmaxf(w_rec[(size_t)k * Hn + j], 0.f);
        if (k == j) w = 0.f;
        w_sm[idx] = (k < NEXC) ? w : -w;
    }
    float br[4];
    #pragma unroll
    for (int jj = 0; jj < 4; jj++) br[jj] = b_rec[jg + jj];
    __syncthreads();

    float h[4], sx[4], su[4];
    #pragma unroll
    for (int jj = 0; jj < 4; jj++) {
        h[jj] = 0.f;
        sx[jj] = 1.f;
        su[jj] = (jj & 1) ? 0.15f : 0.45f;   // jg even -> parity == jj parity
    }

    const ulonglong2* wrow = (const ulonglong2*)w_sm + g;  // element 2k: cols jg..jg+3

    for (int step = 0; step < Tn; step++) {
        // ---- prefetch drive (independent of barrier; coalesced [t][h][b]) ----
        const float* gd = g_drive + ((size_t)step * Hn + jg) * Bn + b;
        float d0 = gd[0], d1 = gd[Bn], d2 = gd[2 * Bn], d3 = gd[3 * Bn];

        // ---- STP update + packed transposed h_post write ----
        float hp[4];
        #pragma unroll
        for (int jj = 0; jj < 4; jj++) {
            const float axv = (jj & 1) ? AX_FAST : AX_SLOW;
            const float Uv  = (jj & 1) ? 0.15f : 0.45f;
            float hh = h[jj];
            float sxo = sx[jj], suo = su[jj];
            float sxn = sxo + axv * (1.f - sxo) - DT_SEC * suo * sxo * hh;
            float sun = suo + axv * (Uv - suo) + DT_SEC * Uv * (1.f - suo) * hh;
            sxn = fminf(fmaxf(sxn, 0.f), 1.f);
            sun = fminf(fmaxf(sun, 0.f), 1.f);
            sx[jj] = sxn; su[jj] = sun;
            hp[jj] = sun * sxn * hh;
        }
        float4* hp4 = (float4*)g_hpT[step & 1];
        hp4[(c * 2 + g) * Bn + b] = make_float4(hp[0], hp[1], hp[2], hp[3]);

        // ---- grid barrier (monotonic phase) ----
        __threadfence();
        __syncthreads();
        if (tid == 0) {
            unsigned target = (unsigned)(step + 1);
            unsigned v = atomicAdd(&g_count, 1u);
            if (v == target * NCTA - 1u) {
                __threadfence();
                g_phase = target;
            } else {
                while (g_phase < target) { }
            }
            __threadfence();
        }
        __syncthreads();

        // ---- GEMM: packed-pair accumulators, fma.rn.f32x2 ----
        unsigned long long a01 = 0ull, a23 = 0ull;
        const float4* hpc = ((const float4*)g_hpT[step & 1]) + b;

        float4 hvA[8], hvB[8];
        #pragma unroll
        for (int u = 0; u < 8; u++) hvA[u] = hpc[u * Bn];

        #define STEPK(vv_, kk_) {                                   \
            ulonglong2 w2 = wrow[(kk_) << 1];                        \
            unsigned long long vp = pack2(vv_);                      \
            a01 = fma2(vp, w2.x, a01);                               \
            a23 = fma2(vp, w2.y, a23); }

        #pragma unroll 1
        for (int kb = 0; kb < Hn; kb += 64) {
            int m0 = kb >> 2;
            #pragma unroll
            for (int u = 0; u < 8; u++) hvB[u] = hpc[(m0 + 8 + u) * Bn];
            #pragma unroll
            for (int u = 0; u < 8; u++) {
                float4 v = hvA[u];
                int k0 = kb + u * 4;
                STEPK(v.x, k0); STEPK(v.y, k0 + 1);
                STEPK(v.z, k0 + 2); STEPK(v.w, k0 + 3);
            }
            if (kb + 64 < Hn) {
                #pragma unroll
                for (int u = 0; u < 8; u++) hvA[u] = hpc[(m0 + 16 + u) * Bn];
            }
            #pragma unroll
            for (int u = 0; u < 8; u++) {
                float4 v = hvB[u];
                int k0 = kb + 32 + u * 4;
                STEPK(v.x, k0); STEPK(v.y, k0 + 1);
                STEPK(v.z, k0 + 2); STEPK(v.w, k0 + 3);
            }
        }
        #undef STEPK

        float acc[4];
        unpack2(a01, acc[0], acc[1]);
        unpack2(a23, acc[2], acc[3]);

        // ---- h update + acts write (drive already includes 0.25*noise) ----
        float dd[4] = {d0, d1, d2, d3};
        float hn[4];
        #pragma unroll
        for (int jj = 0; jj < 4; jj++) {
            float val = h[jj] * (1.f - ALPHA_N)
                      + ALPHA_N * (dd[jj] + acc[jj] + br[jj]);
            hn[jj] = fmaxf(val, 0.f);
            h[jj] = hn[jj];
        }
        float4* ao = (float4*)(acts + ((size_t)b * Tn + step) * Hn + jg);
        *ao = make_float4(hn[0], hn[1], hn[2], hn[3]);
    }
}

// ---------------- post: fused readout, comb in smem, 32 rows/block ----------------
#define PR_ROWS 32
__global__ void __launch_bounds__(256) post_kernel(const float* __restrict__ acts,
                                                   float* __restrict__ out0,
                                                   float* __restrict__ pout) {
    extern __shared__ float s_comb[];        // NR * Hn floats (108 KB)
    const int tid = threadIdx.x;
    for (int i = tid; i < NR * Hn; i += 256) s_comb[i] = g_comb[i];
    __syncthreads();

    const int wid = tid >> 5, lane = tid & 31;
    const float4* comb4 = (const float4*)s_comb;

    #pragma unroll 1
    for (int rr = 0; rr < 4; rr++) {
        const int bt = blockIdx.x * PR_ROWS + wid * 4 + rr;
        const float4* a4 = (const float4*)(acts + (size_t)bt * Hn);

        float acc[NR];
        #pragma unroll
        for (int r = 0; r < NR; r++) acc[r] = 0.f;

        #pragma unroll
        for (int it = 0; it < Hn / 128; it++) {
            float4 a = a4[it * 32 + lane];
            #pragma unroll
            for (int r = 0; r < NR; r++) {
                float4 w = comb4[r * 256 + it * 32 + lane];
                float s = a.x * w.x + a.y * w.y;
                s = fmaf(a.z, w.z, s);
                s = fmaf(a.w, w.w, s);
                acc[r] += s;
            }
        }
        #pragma unroll
        for (int r = 0; r < NR; r++) {
            #pragma unroll
            for (int off = 16; off > 0; off >>= 1)
                acc[r] += __shfl_down_sync(0xffffffffu, acc[r], off);
        }
        if (lane == 0) {
            #pragma unroll
            for (int r = 0; r < NOUTn; r++)
                out0[(size_t)bt * NOUTn + r] = acc[r] + g_combb[r];
            #pragma unroll
            for (int r = NOUTn; r < NR; r++)
                pout[(size_t)bt * (NCLSn * CLSOUTn) + (r - NOUTn)] = acc[r] + g_combb[r];
        }
    }
}

// ---------------- launch ----------------
extern "C" void kernel_launch(void* const* d_in, const int* in_sizes, int n_in,
                              void* d_out, int out_size) {
    const float* stim  = (const float*)d_in[0];
    const float* ctx   = (const float*)d_in[1];
    const float* w_rec = (const float*)d_in[2];
    const float* b_rec = (const float*)d_in[3];
    const float* w_in  = (const float*)d_in[4];
    const float* w_ctx = (const float*)d_in[5];
    const float* w_out = (const float*)d_in[6];
    const float* b_out = (const float*)d_in[7];
    const float* c1_w  = (const float*)d_in[8];
    const float* c1_b  = (const float*)d_in[9];
    const float* c2_w  = (const float*)d_in[10];
    const float* c2_b  = (const float*)d_in[11];
    const float* noise = (const float*)d_in[12];

    float* out0 = (float*)d_out;                         // [B, T, 3]
    float* acts = out0 + (size_t)Bn * Tn * NOUTn;        // [B, T, H]
    float* pout = acts + (size_t)Bn * Tn * Hn;           // [B, T, 3, 8]

    prep_kernel<<<256, 256>>>(w_out, b_out, c1_w, c1_b, c2_w, c2_b);

    dim3 dgrid(Tn, Hn / 256);
    drive_kernel<<<dgrid, 256>>>(stim, ctx, noise, w_in, w_ctx);

    scan_kernel<<<NCTA, 256>>>(w_rec, b_rec, acts);

    static bool attr_set = false;
    if (!attr_set) {
        cudaFuncSetAttribute(post_kernel,
                             cudaFuncAttributeMaxDynamicSharedMemorySize,
                             NR * Hn * (int)sizeof(float));
        attr_set = true;
    }
    post_kernel<<<(Bn * Tn) / PR_ROWS, 256, NR * Hn * sizeof(float)>>>(acts, out0, pout);
}

// round 4
// speedup vs baseline: 1.2478x; 1.1672x over previous
#include <cuda_runtime.h>
#include <cuda_bf16.h>
#include <cstdint>

// Problem constants
#define Hn 1024
#define Bn 128
#define Tn 400
#define Sn 64
#define Cn 8
#define NOUTn 3
#define NCLSn 3
#define BOTn 2
#define CLSOUTn 8
#define NEXC 819              // int(1024 * 0.8)

#define NCTA 128
#define JPC 8                 // j columns per CTA in phase B
#define KSL 128               // k-slice per CTA in phase A
#define JSL 64                // j-slice per CTA in phase A
#define NKC 8                 // number of k slices

#define ALPHA_N 0.2f
#define DT_SEC 0.02f
#define NZ_SCALE 0.25f        // NOISE_STD / ALPHA_N
#define AX_SLOW ((float)(20.0 / 1500.0))
#define AX_FAST ((float)(20.0 / 200.0))

#define NR (NOUTn + NCLSn * CLSOUTn)   // 27 fused readout rows

// ---------------- device scratch ----------------
__device__ float g_drive[(size_t)Tn * Hn * Bn];   // [t][h][b], noise folded in
__device__ float g_hpT[Hn * Bn];                  // h_post transposed [k][b]
__device__ float g_part[(size_t)NKC * Hn * Bn];   // [kc][j][b] partial sums (4MB)
__device__ float g_comb[NR * Hn];
__device__ float g_combb[NR];
__device__ unsigned g_count;
__device__ volatile unsigned g_phase;

// ---------------- packed f32x2 helpers ----------------
__device__ __forceinline__ unsigned long long fma2(unsigned long long a,
                                                   unsigned long long b,
                                                   unsigned long long c) {
    unsigned long long d;
    asm("fma.rn.f32x2 %0, %1, %2, %3;" : "=l"(d) : "l"(a), "l"(b), "l"(c));
    return d;
}
__device__ __forceinline__ unsigned long long pack2(float v) {
    unsigned long long d;
    unsigned r = __float_as_uint(v);
    asm("mov.b64 %0, {%1, %2};" : "=l"(d) : "r"(r), "r"(r));
    return d;
}
__device__ __forceinline__ void unpack2(unsigned long long p, float& lo, float& hi) {
    unsigned a, b;
    asm("mov.b64 {%0, %1}, %2;" : "=r"(a), "=r"(b) : "l"(p));
    lo = __uint_as_float(a);
    hi = __uint_as_float(b);
}
__device__ __forceinline__ void cp_async16(uint32_t saddr, const void* gaddr) {
    asm volatile("cp.async.cg.shared.global [%0], [%1], 16;" :: "r"(saddr), "l"(gaddr));
}
__device__ __forceinline__ void cp_commit() {
    asm volatile("cp.async.commit_group;");
}
template <int N>
__device__ __forceinline__ void cp_wait() {
    asm volatile("cp.async.wait_group %0;" :: "n"(N));
}

// ---------------- grid barrier ----------------
__device__ __forceinline__ void grid_barrier(unsigned target) {
    __threadfence();
    __syncthreads();
    if (threadIdx.x == 0) {
        unsigned v = atomicAdd(&g_count, 1u);
        if (v == target * NCTA - 1u) {
            __threadfence();
            g_phase = target;
        } else {
            while (g_phase < target) { }
        }
        __threadfence();
    }
    __syncthreads();
}

// ---------------- prep: reset barrier, fuse classifiers ----------------
__global__ void prep_kernel(const float* __restrict__ w_out,
                            const float* __restrict__ b_out,
                            const float* __restrict__ c1_w,
                            const float* __restrict__ c1_b,
                            const float* __restrict__ c2_w,
                            const float* __restrict__ c2_b) {
    int idx = blockIdx.x * blockDim.x + threadIdx.x;
    if (idx == 0) { g_count = 0; g_phase = 0; }

    if (idx < NOUTn * Hn) g_comb[idx] = w_out[idx];
    if (idx < NCLSn * CLSOUTn * Hn) {
        int r = idx / Hn, h = idx % Hn;
        int j = r / CLSOUTn, o = r % CLSOUTn;
        float acc = 0.f;
        #pragma unroll
        for (int k = 0; k < BOTn; k++)
            acc += c2_w[(j * CLSOUTn + o) * BOTn + k] * c1_w[(j * BOTn + k) * Hn + h];
        g_comb[(NOUTn + r) * Hn + h] = acc;
    }
    if (idx < NOUTn) g_combb[idx] = b_out[idx];
    if (idx >= NOUTn && idx < NR) {
        int r = idx - NOUTn;
        int j = r / CLSOUTn, o = r % CLSOUTn;
        float acc = c2_b[j * CLSOUTn + o];
        #pragma unroll
        for (int k = 0; k < BOTn; k++)
            acc += c2_w[(j * CLSOUTn + o) * BOTn + k] * c1_b[j * BOTn + k];
        g_combb[idx] = acc;
    }
}

// ---------------- drive: g_drive[t][h][b] = stim@w_in^T + ctx@w_ctx^T + 0.25*noise ----
__global__ void __launch_bounds__(256) drive_kernel(
        const float* __restrict__ stim,
        const float* __restrict__ ctx,
        const float* __restrict__ noise,
        const float* __restrict__ w_in,
        const float* __restrict__ w_ctx) {
    const int t = blockIdx.x;
    const int g = threadIdx.x >> 7;
    const int b = threadIdx.x & 127;
    const int h0 = blockIdx.y * 256 + g * 128;

    float sin_r[Sn], cin_r[Cn];
    const float4* sp = (const float4*)(stim + ((size_t)b * Tn + t) * Sn);
    #pragma unroll
    for (int q = 0; q < Sn / 4; q++) {
        float4 v = sp[q];
        sin_r[4*q] = v.x; sin_r[4*q+1] = v.y; sin_r[4*q+2] = v.z; sin_r[4*q+3] = v.w;
    }
    const float4* cp = (const float4*)(ctx + ((size_t)b * Tn + t) * Cn);
    #pragma unroll
    for (int q = 0; q < Cn / 4; q++) {
        float4 v = cp[q];
        cin_r[4*q] = v.x; cin_r[4*q+1] = v.y; cin_r[4*q+2] = v.z; cin_r[4*q+3] = v.w;
    }
    const float4* nzp = (const float4*)(noise + ((size_t)t * Bn + b) * Hn);

    for (int hh = 0; hh < 128; hh += 4) {
        const int h = h0 + hh;
        float acc0 = 0.f, acc1 = 0.f, acc2 = 0.f, acc3 = 0.f;
        #pragma unroll
        for (int s4 = 0; s4 < Sn / 4; s4++) {
            float4 w0 = *(const float4*)(w_in + (size_t)(h + 0) * Sn + s4 * 4);
            float4 w1 = *(const float4*)(w_in + (size_t)(h + 1) * Sn + s4 * 4);
            float4 w2 = *(const float4*)(w_in + (size_t)(h + 2) * Sn + s4 * 4);
            float4 w3 = *(const float4*)(w_in + (size_t)(h + 3) * Sn + s4 * 4);
            float i0 = sin_r[4*s4], i1 = sin_r[4*s4+1], i2 = sin_r[4*s4+2], i3 = sin_r[4*s4+3];
            acc0 = fmaf(i0, w0.x, acc0); acc0 = fmaf(i1, w0.y, acc0);
            acc0 = fmaf(i2, w0.z, acc0); acc0 = fmaf(i3, w0.w, acc0);
            acc1 = fmaf(i0, w1.x, acc1); acc1 = fmaf(i1, w1.y, acc1);
            acc1 = fmaf(i2, w1.z, acc1); acc1 = fmaf(i3, w1.w, acc1);
            acc2 = fmaf(i0, w2.x, acc2); acc2 = fmaf(i1, w2.y, acc2);
            acc2 = fmaf(i2, w2.z, acc2); acc2 = fmaf(i3, w2.w, acc2);
            acc3 = fmaf(i0, w3.x, acc3); acc3 = fmaf(i1, w3.y, acc3);
            acc3 = fmaf(i2, w3.z, acc3); acc3 = fmaf(i3, w3.w, acc3);
        }
        #pragma unroll
        for (int c4 = 0; c4 < Cn / 4; c4++) {
            float4 w0 = *(const float4*)(w_ctx + (size_t)(h + 0) * Cn + c4 * 4);
            float4 w1 = *(const float4*)(w_ctx + (size_t)(h + 1) * Cn + c4 * 4);
            float4 w2 = *(const float4*)(w_ctx + (size_t)(h + 2) * Cn + c4 * 4);
            float4 w3 = *(const float4*)(w_ctx + (size_t)(h + 3) * Cn + c4 * 4);
            float i0 = cin_r[4*c4], i1 = cin_r[4*c4+1], i2 = cin_r[4*c4+2], i3 = cin_r[4*c4+3];
            acc0 = fmaf(i0, w0.x, acc0); acc0 = fmaf(i1, w0.y, acc0);
            acc0 = fmaf(i2, w0.z, acc0); acc0 = fmaf(i3, w0.w, acc0);
            acc1 = fmaf(i0, w1.x, acc1); acc1 = fmaf(i1, w1.y, acc1);
            acc1 = fmaf(i2, w1.z, acc1); acc1 = fmaf(i3, w1.w, acc1);
            acc2 = fmaf(i0, w2.x, acc2); acc2 = fmaf(i1, w2.y, acc2);
            acc2 = fmaf(i2, w2.z, acc2); acc2 = fmaf(i3, w2.w, acc2);
            acc3 = fmaf(i0, w3.x, acc3); acc3 = fmaf(i1, w3.y, acc3);
            acc3 = fmaf(i2, w3.z, acc3); acc3 = fmaf(i3, w3.w, acc3);
        }
        float4 nz = nzp[h >> 2];
        float* gd = g_drive + ((size_t)t * Hn + h) * Bn + b;
        gd[0]        = fmaf(NZ_SCALE, nz.x, acc0);
        gd[Bn]       = fmaf(NZ_SCALE, nz.y, acc1);
        gd[2 * Bn]   = fmaf(NZ_SCALE, nz.z, acc2);
        gd[3 * Bn]   = fmaf(NZ_SCALE, nz.w, acc3);
    }
}

// ---------------- persistent scan kernel: split-K GEMM + reduce ----------------
// Phase A: CTA(kc=c>>4, jc=c&15) computes partial[b, jslice] over its 128-k slice.
// Phase B: CTA c owns j-slice [c*8, c*8+8): reduce 8 partials, h-update, STP.
#define SMEM_SCAN ((KSL * JSL + KSL * Bn) * 4)   // 32KB W + 64KB h_post stage

__global__ void __launch_bounds__(256, 1) scan_kernel(
        const float* __restrict__ w_rec,
        const float* __restrict__ b_rec,
        float* __restrict__ acts) {
    extern __shared__ float sm[];
    float* w_sm  = sm;                 // [128][64]
    float* hp_sm = sm + KSL * JSL;     // [128][128]

    const int c   = blockIdx.x;
    const int tid = threadIdx.x;
    // phase A roles
    const int kc = c >> 4, jc = c & 15;
    const int q  = tid & 31;           // b-quad: b = 4q..4q+3
    const int w  = tid >> 5;           // j-octet: j_local = w*8..w*8+8
    // phase B roles
    const int b  = tid & 127;
    const int g  = tid >> 7;
    const int j0 = c * JPC;
    const int jg = j0 + 4 * g;

    // W slice [kc*128..+128) x [jc*64..+64): sign * relu * no-diag
    for (int idx = tid; idx < KSL * JSL; idx += 256) {
        int kl = idx >> 6, jl = idx & 63;
        int k = kc * KSL + kl, j = jc * JSL + jl;
        float ww = fmaxf(w_rec[(size_t)k * Hn + j], 0.f);
        if (k == j) ww = 0.f;
        w_sm[idx] = (k < NEXC) ? ww : -ww;
    }
    float br[4];
    #pragma unroll
    for (int jj = 0; jj < 4; jj++) br[jj] = b_rec[jg + jj];

    // state (phase B)
    float h[4], sx[4], su[4];
    #pragma unroll
    for (int jj = 0; jj < 4; jj++) {
        h[jj] = 0.f;
        sx[jj] = 1.f;
        su[jj] = (jj & 1) ? 0.15f : 0.45f;
    }
    // h_post(0) = 0 (STP step on h=0 leaves sx=1, su=U)
    #pragma unroll
    for (int jj = 0; jj < 4; jj++) g_hpT[(jg + jj) * Bn + b] = 0.f;

    unsigned bar = 0;
    grid_barrier(++bar);

    const uint32_t hp_sm_addr = (uint32_t)__cvta_generic_to_shared(hp_sm);

    for (int step = 0; step < Tn; step++) {
        // prefetch drive for phase B (coalesced, independent)
        const float* gd = g_drive + ((size_t)step * Hn + jg) * Bn + b;
        float d0 = gd[0], d1 = gd[Bn], d2 = gd[2 * Bn], d3 = gd[3 * Bn];

        // ---- phase A: stage h_post k-slice into smem (L1-bypassing cp.async) ----
        // two chunks of 64 k-rows (32KB each), double buffered
        {
            const float* src0 = g_hpT + (size_t)(kc * KSL) * Bn;
            #pragma unroll
            for (int i = 0; i < 8; i++) {
                int s = tid + i * 256;               // slot in chunk0
                cp_async16(hp_sm_addr + s * 16, src0 + s * 4);
            }
            cp_commit();
            #pragma unroll
            for (int i = 0; i < 8; i++) {
                int s = tid + i * 256;               // slot in chunk1
                cp_async16(hp_sm_addr + 32768 + s * 16, src0 + 8192 + s * 4);
            }
            cp_commit();
        }

        unsigned long long acc[4][4];
        #pragma unroll
        for (int bi = 0; bi < 4; bi++)
            #pragma unroll
            for (int jp = 0; jp < 4; jp++) acc[bi][jp] = 0ull;

        cp_wait<1>();
        __syncthreads();

        #pragma unroll 4
        for (int kl = 0; kl < 64; kl++) {
            float4 hp = *(const float4*)(hp_sm + kl * Bn + 4 * q);
            const ulonglong2* wp = (const ulonglong2*)(w_sm + kl * JSL + w * 8);
            ulonglong2 w01 = wp[0], w23 = wp[1];
            unsigned long long p0 = pack2(hp.x), p1 = pack2(hp.y);
            unsigned long long p2 = pack2(hp.z), p3 = pack2(hp.w);
            acc[0][0] = fma2(p0, w01.x, acc[0][0]); acc[0][1] = fma2(p0, w01.y, acc[0][1]);
            acc[0][2] = fma2(p0, w23.x, acc[0][2]); acc[0][3] = fma2(p0, w23.y, acc[0][3]);
            acc[1][0] = fma2(p1, w01.x, acc[1][0]); acc[1][1] = fma2(p1, w01.y, acc[1][1]);
            acc[1][2] = fma2(p1, w23.x, acc[1][2]); acc[1][3] = fma2(p1, w23.y, acc[1][3]);
            acc[2][0] = fma2(p2, w01.x, acc[2][0]); acc[2][1] = fma2(p2, w01.y, acc[2][1]);
            acc[2][2] = fma2(p2, w23.x, acc[2][2]); acc[2][3] = fma2(p2, w23.y, acc[2][3]);
            acc[3][0] = fma2(p3, w01.x, acc[3][0]); acc[3][1] = fma2(p3, w01.y, acc[3][1]);
            acc[3][2] = fma2(p3, w23.x, acc[3][2]); acc[3][3] = fma2(p3, w23.y, acc[3][3]);
        }

        cp_wait<0>();
        __syncthreads();

        #pragma unroll 4
        for (int kl = 64; kl < 128; kl++) {
            float4 hp = *(const float4*)(hp_sm + kl * Bn + 4 * q);
            const ulonglong2* wp = (const ulonglong2*)(w_sm + kl * JSL + w * 8);
            ulonglong2 w01 = wp[0], w23 = wp[1];
            unsigned long long p0 = pack2(hp.x), p1 = pack2(hp.y);
            unsigned long long p2 = pack2(hp.z), p3 = pack2(hp.w);
            acc[0][0] = fma2(p0, w01.x, acc[0][0]); acc[0][1] = fma2(p0, w01.y, acc[0][1]);
            acc[0][2] = fma2(p0, w23.x, acc[0][2]); acc[0][3] = fma2(p0, w23.y, acc[0][3]);
            acc[1][0] = fma2(p1, w01.x, acc[1][0]); acc[1][1] = fma2(p1, w01.y, acc[1][1]);
            acc[1][2] = fma2(p1, w23.x, acc[1][2]); acc[1][3] = fma2(p1, w23.y, acc[1][3]);
            acc[2][0] = fma2(p2, w01.x, acc[2][0]); acc[2][1] = fma2(p2, w01.y, acc[2][1]);
            acc[2][2] = fma2(p2, w23.x, acc[2][2]); acc[2][3] = fma2(p2, w23.y, acc[2][3]);
            acc[3][0] = fma2(p3, w01.x, acc[3][0]); acc[3][1] = fma2(p3, w01.y, acc[3][1]);
            acc[3][2] = fma2(p3, w23.x, acc[3][2]); acc[3][3] = fma2(p3, w23.y, acc[3][3]);
        }

        // write partials [kc][j][b], float4 over b
        #pragma unroll
        for (int jp = 0; jp < 4; jp++) {
            float l0, h0v, l1, h1v, l2, h2v, l3, h3v;
            unpack2(acc[0][jp], l0, h0v);
            unpack2(acc[1][jp], l1, h1v);
            unpack2(acc[2][jp], l2, h2v);
            unpack2(acc[3][jp], l3, h3v);
            int j = jc * JSL + w * 8 + 2 * jp;
            *(float4*)(g_part + ((size_t)kc * Hn + j) * Bn + 4 * q) =
                make_float4(l0, l1, l2, l3);
            *(float4*)(g_part + ((size_t)kc * Hn + j + 1) * Bn + 4 * q) =
                make_float4(h0v, h1v, h2v, h3v);
        }

        grid_barrier(++bar);

        // ---- phase B: reduce partials, h-update, STP, write h_post ----
        float s0 = 0.f, s1 = 0.f, s2 = 0.f, s3 = 0.f;
        #pragma unroll
        for (int k2 = 0; k2 < NKC; k2++) {
            const float* pp = g_part + ((size_t)k2 * Hn + jg) * Bn + b;
            s0 += __ldcg(pp);
            s1 += __ldcg(pp + Bn);
            s2 += __ldcg(pp + 2 * Bn);
            s3 += __ldcg(pp + 3 * Bn);
        }
        float ss[4] = {s0, s1, s2, s3};
        float dd[4] = {d0, d1, d2, d3};
        float hn[4];
        #pragma unroll
        for (int jj = 0; jj < 4; jj++) {
            float val = h[jj] * (1.f - ALPHA_N)
                      + ALPHA_N * (dd[jj] + ss[jj] + br[jj]);
            hn[jj] = fmaxf(val, 0.f);
            h[jj] = hn[jj];
        }
        *(float4*)(acts + ((size_t)b * Tn + step) * Hn + jg) =
            make_float4(hn[0], hn[1], hn[2], hn[3]);

        if (step + 1 < Tn) {
            #pragma unroll
            for (int jj = 0; jj < 4; jj++) {
                const float axv = (jj & 1) ? AX_FAST : AX_SLOW;
                const float Uv  = (jj & 1) ? 0.15f : 0.45f;
                float hh = h[jj];
                float sxo = sx[jj], suo = su[jj];
                float sxn = sxo + axv * (1.f - sxo) - DT_SEC * suo * sxo * hh;
                float sun = suo + axv * (Uv - suo) + DT_SEC * Uv * (1.f - suo) * hh;
                sxn = fminf(fmaxf(sxn, 0.f), 1.f);
                sun = fminf(fmaxf(sun, 0.f), 1.f);
                sx[jj] = sxn; su[jj] = sun;
                g_hpT[(jg + jj) * Bn + b] = sun * sxn * hh;
            }
            grid_barrier(++bar);
        }
    }
}

// ---------------- post: fused readout, comb in smem ----------------
#define PR_ROWS 32
__global__ void __launch_bounds__(256) post_kernel(const float* __restrict__ acts,
                                                   float* __restrict__ out0,
                                                   float* __restrict__ pout) {
    extern __shared__ float s_comb[];        // NR * Hn floats (108 KB)
    const int tid = threadIdx.x;
    for (int i = tid; i < NR * Hn; i += 256) s_comb[i] = g_comb[i];
    __syncthreads();

    const int wid = tid >> 5, lane = tid & 31;
    const float4* comb4 = (const float4*)s_comb;

    #pragma unroll 1
    for (int rr = 0; rr < 4; rr++) {
        const int bt = blockIdx.x * PR_ROWS + wid * 4 + rr;
        const float4* a4 = (const float4*)(acts + (size_t)bt * Hn);

        float acc[NR];
        #pragma unroll
        for (int r = 0; r < NR; r++) acc[r] = 0.f;

        #pragma unroll
        for (int it = 0; it < Hn / 128; it++) {
            float4 a = a4[it * 32 + lane];
            #pragma unroll
            for (int r = 0; r < NR; r++) {
                float4 w = comb4[r * 256 + it * 32 + lane];
                float s = a.x * w.x + a.y * w.y;
                s = fmaf(a.z, w.z, s);
                s = fmaf(a.w, w.w, s);
                acc[r] += s;
            }
        }
        #pragma unroll
        for (int r = 0; r < NR; r++) {
            #pragma unroll
            for (int off = 16; off > 0; off >>= 1)
                acc[r] += __shfl_down_sync(0xffffffffu, acc[r], off);
        }
        if (lane == 0) {
            #pragma unroll
            for (int r = 0; r < NOUTn; r++)
                out0[(size_t)bt * NOUTn + r] = acc[r] + g_combb[r];
            #pragma unroll
            for (int r = NOUTn; r < NR; r++)
                pout[(size_t)bt * (NCLSn * CLSOUTn) + (r - NOUTn)] = acc[r] + g_combb[r];
        }
    }
}

// ---------------- launch ----------------
extern "C" void kernel_launch(void* const* d_in, const int* in_sizes, int n_in,
                              void* d_out, int out_size) {
    const float* stim  = (const float*)d_in[0];
    const float* ctx   = (const float*)d_in[1];
    const float* w_rec = (const float*)d_in[2];
    const float* b_rec = (const float*)d_in[3];
    const float* w_in  = (const float*)d_in[4];
    const float* w_ctx = (const float*)d_in[5];
    const float* w_out = (const float*)d_in[6];
    const float* b_out = (const float*)d_in[7];
    const float* c1_w  = (const float*)d_in[8];
    const float* c1_b  = (const float*)d_in[9];
    const float* c2_w  = (const float*)d_in[10];
    const float* c2_b  = (const float*)d_in[11];
    const float* noise = (const float*)d_in[12];

    float* out0 = (float*)d_out;                         // [B, T, 3]
    float* acts = out0 + (size_t)Bn * Tn * NOUTn;        // [B, T, H]
    float* pout = acts + (size_t)Bn * Tn * Hn;           // [B, T, 3, 8]

    static bool attr_set = false;
    if (!attr_set) {
        cudaFuncSetAttribute(post_kernel,
                             cudaFuncAttributeMaxDynamicSharedMemorySize,
                             NR * Hn * (int)sizeof(float));
        cudaFuncSetAttribute(scan_kernel,
                             cudaFuncAttributeMaxDynamicSharedMemorySize,
                             SMEM_SCAN);
        attr_set = true;
    }

    prep_kernel<<<256, 256>>>(w_out, b_out, c1_w, c1_b, c2_w, c2_b);

    dim3 dgrid(Tn, Hn / 256);
    drive_kernel<<<dgrid, 256>>>(stim, ctx, noise, w_in, w_ctx);

    scan_kernel<<<NCTA, 256, SMEM_SCAN>>>(w_rec, b_rec, acts);

    post_kernel<<<(Bn * Tn) / PR_ROWS, 256, NR * Hn * sizeof(float)>>>(acts, out0, pout);
}

// round 6
// speedup vs baseline: 1.3141x; 1.0531x over previous
#include <cuda_runtime.h>
#include <cuda_bf16.h>
#include <cstdint>

// Problem constants
#define Hn 1024
#define Bn 128
#define Tn 400
#define Sn 64
#define Cn 8
#define NOUTn 3
#define NCLSn 3
#define BOTn 2
#define CLSOUTn 8
#define NEXC 819              // int(1024 * 0.8)

#define NCTA 128
#define JPC 8                 // j columns per CTA in phase B
#define KSL 128               // k-slice per CTA in phase A
#define JSL 64                // j-slice per CTA in phase A
#define NKC 8                 // number of k slices

#define ALPHA_N 0.2f
#define DT_SEC 0.02f
#define NZ_SCALE 0.25f        // NOISE_STD / ALPHA_N
#define AX_SLOW ((float)(20.0 / 1500.0))
#define AX_FAST ((float)(20.0 / 200.0))

#define NR (NOUTn + NCLSn * CLSOUTn)   // 27 fused readout rows
#define PR_ROWS 32

// smem layout (floats): w_sm[8192] | hp_sm[16384] | comb[27*1024]
#define SM_W 0
#define SM_HP 8192
#define SM_COMB (8192 + 16384)
#define SMEM_BYTES ((8192 + 16384 + NR * Hn) * 4)

// ---------------- device scratch ----------------
__device__ float g_drive[(size_t)Tn * Hn * Bn];        // [t][h][b], noise folded
__device__ float g_hp[2][Hn * Bn];                     // h_post [k][b], double buffered
__device__ float g_part[2][(size_t)NKC * Hn * Bn];     // [par][kc][j][b]
__device__ float g_comb[NR * Hn];
__device__ float g_combb[NR];
__device__ unsigned g_count;                           // phase-transition counter
__device__ unsigned g_kcnt[NKC * 32];                  // partial-ready counts (padded)
__device__ unsigned g_hcnt[NKC * 32];                  // h_post-ready counts (padded)

// ---------------- sync helpers (morally-strong release/acquire) ----------------
__device__ __forceinline__ void red_rel(unsigned* p) {
    asm volatile("red.release.gpu.global.add.u32 [%0], 1;" :: "l"(p) : "memory");
}
__device__ __forceinline__ unsigned ld_acq(const unsigned* p) {
    unsigned v;
    asm volatile("ld.acquire.gpu.global.u32 %0, [%1];" : "=r"(v) : "l"(p) : "memory");
    return v;
}
// announce: drain all CTA stores, then one release-increment
__device__ __forceinline__ void announce(unsigned* p) {
    __threadfence();
    __syncthreads();
    if (threadIdx.x == 0) red_rel(p);
}

// ---------------- packed f32x2 helpers ----------------
__device__ __forceinline__ unsigned long long fma2(unsigned long long a,
                                                   unsigned long long b,
                                                   unsigned long long c) {
    unsigned long long d;
    asm("fma.rn.f32x2 %0, %1, %2, %3;" : "=l"(d) : "l"(a), "l"(b), "l"(c));
    return d;
}
__device__ __forceinline__ unsigned long long pack2(float v) {
    unsigned long long d;
    unsigned r = __float_as_uint(v);
    asm("mov.b64 %0, {%1, %2};" : "=l"(d) : "r"(r), "r"(r));
    return d;
}
__device__ __forceinline__ void unpack2(unsigned long long p, float& lo, float& hi) {
    unsigned a, b;
    asm("mov.b64 {%0, %1}, %2;" : "=r"(a), "=r"(b) : "l"(p));
    lo = __uint_as_float(a);
    hi = __uint_as_float(b);
}
__device__ __forceinline__ void cp_async16(uint32_t saddr, const void* gaddr) {
    asm volatile("cp.async.cg.shared.global [%0], [%1], 16;" :: "r"(saddr), "l"(gaddr));
}
__device__ __forceinline__ void cp_commit() {
    asm volatile("cp.async.commit_group;");
}
template <int N>
__device__ __forceinline__ void cp_wait() {
    asm volatile("cp.async.wait_group %0;" :: "n"(N));
}

// generic phase-transition barrier: cumulative arrival target
__device__ __forceinline__ void gbar(unsigned target) {
    __threadfence();
    __syncthreads();
    if (threadIdx.x == 0) {
        red_rel(&g_count);
        while (ld_acq(&g_count) < target) { }
    }
    __syncthreads();
}

// ---------------- reset (graph-replay determinism) ----------------
__global__ void reset_kernel() {
    int i = threadIdx.x;
    if (i == 0) g_count = 0;
    if (i < NKC * 32) { g_kcnt[i] = 0; g_hcnt[i] = 0; }
}

// ---------------- the single persistent kernel ----------------
__global__ void __launch_bounds__(256, 1) mega_kernel(
        const float* __restrict__ stim,
        const float* __restrict__ ctx,
        const float* __restrict__ w_rec,
        const float* __restrict__ b_rec,
        const float* __restrict__ w_in,
        const float* __restrict__ w_ctx,
        const float* __restrict__ w_out,
        const float* __restrict__ b_out,
        const float* __restrict__ c1_w,
        const float* __restrict__ c1_b,
        const float* __restrict__ c2_w,
        const float* __restrict__ c2_b,
        const float* __restrict__ noise,
        float* __restrict__ out0,
        float* __restrict__ acts,
        float* __restrict__ pout) {
    extern __shared__ float sm[];
    float* w_sm  = sm + SM_W;     // [128][64]
    float* hp_sm = sm + SM_HP;    // [128][128]

    const int c   = blockIdx.x;
    const int tid = threadIdx.x;
    // phase A roles
    const int kc = c >> 4, jc = c & 15;
    const int q  = tid & 31;              // b-quad
    const int w  = tid >> 5;              // j-octet
    const int kc32 = kc * 32;
    // phase B roles
    const int b  = tid & 127;
    const int g  = tid >> 7;
    const int j0 = c * JPC;
    const int jg = j0 + 4 * g;
    const int hg32 = (c >> 4) * 32;       // h_post producer group (== kc32)

    // ---- P0a: classifier fusion (one pass, unique idx per thread) ----
    {
        int idx = c * 256 + tid;
        if (idx < NOUTn * Hn) g_comb[idx] = w_out[idx];
        if (idx < NCLSn * CLSOUTn * Hn) {
            int r = idx / Hn, h = idx % Hn;
            int j = r / CLSOUTn, o = r % CLSOUTn;
            float acc = 0.f;
            #pragma unroll
            for (int k = 0; k < BOTn; k++)
                acc += c2_w[(j * CLSOUTn + o) * BOTn + k] * c1_w[(j * BOTn + k) * Hn + h];
            g_comb[(NOUTn + r) * Hn + h] = acc;
        }
        if (idx < NOUTn) g_combb[idx] = b_out[idx];
        if (idx >= NOUTn && idx < NR) {
            int r = idx - NOUTn;
            int j = r / CLSOUTn, o = r % CLSOUTn;
            float acc = c2_b[j * CLSOUTn + o];
            #pragma unroll
            for (int k = 0; k < BOTn; k++)
                acc += c2_w[(j * CLSOUTn + o) * BOTn + k] * c1_b[j * BOTn + k];
            g_combb[idx] = acc;
        }
    }

    // ---- P0b: W slice into smem ----
    for (int idx = tid; idx < KSL * JSL; idx += 256) {
        int kl = idx >> 6, jl = idx & 63;
        int k = kc * KSL + kl, j = jc * JSL + jl;
        float ww = fmaxf(w_rec[(size_t)k * Hn + j], 0.f);
        if (k == j) ww = 0.f;
        w_sm[idx] = (k < NEXC) ? ww : -ww;
    }
    float br[4];
    #pragma unroll
    for (int jj = 0; jj < 4; jj++) br[jj] = b_rec[jg + jj];

    // ---- P0c: initial h_post(0) = 0, announce ----
    #pragma unroll
    for (int jj = 0; jj < 4; jj++) g_hp[0][(jg + jj) * Bn + b] = 0.f;
    announce(&g_hcnt[hg32]);

    // ---- P1: drive precompute, grid-stride over 1600 (t, 256h) units ----
    {
        const int gg = tid >> 7;
        const int bb = tid & 127;
        for (int u = c; u < Tn * 4; u += NCTA) {
            const int t = u % Tn;
            const int h0 = (u / Tn) * 256 + gg * 128;

            float sin_r[Sn], cin_r[Cn];
            const float4* sp = (const float4*)(stim + ((size_t)bb * Tn + t) * Sn);
            #pragma unroll
            for (int p = 0; p < Sn / 4; p++) {
                float4 v = sp[p];
                sin_r[4*p] = v.x; sin_r[4*p+1] = v.y; sin_r[4*p+2] = v.z; sin_r[4*p+3] = v.w;
            }
            const float4* cpp = (const float4*)(ctx + ((size_t)bb * Tn + t) * Cn);
            #pragma unroll
            for (int p = 0; p < Cn / 4; p++) {
                float4 v = cpp[p];
                cin_r[4*p] = v.x; cin_r[4*p+1] = v.y; cin_r[4*p+2] = v.z; cin_r[4*p+3] = v.w;
            }
            const float4* nzp = (const float4*)(noise + ((size_t)t * Bn + bb) * Hn);

            for (int hh = 0; hh < 128; hh += 4) {
                const int h = h0 + hh;
                float acc0 = 0.f, acc1 = 0.f, acc2 = 0.f, acc3 = 0.f;
                #pragma unroll
                for (int s4 = 0; s4 < Sn / 4; s4++) {
                    float4 w0 = *(const float4*)(w_in + (size_t)(h + 0) * Sn + s4 * 4);
                    float4 w1 = *(const float4*)(w_in + (size_t)(h + 1) * Sn + s4 * 4);
                    float4 w2 = *(const float4*)(w_in + (size_t)(h + 2) * Sn + s4 * 4);
                    float4 w3 = *(const float4*)(w_in + (size_t)(h + 3) * Sn + s4 * 4);
                    float i0 = sin_r[4*s4], i1 = sin_r[4*s4+1];
                    float i2 = sin_r[4*s4+2], i3 = sin_r[4*s4+3];
                    acc0 = fmaf(i0, w0.x, acc0); acc0 = fmaf(i1, w0.y, acc0);
                    acc0 = fmaf(i2, w0.z, acc0); acc0 = fmaf(i3, w0.w, acc0);
                    acc1 = fmaf(i0, w1.x, acc1); acc1 = fmaf(i1, w1.y, acc1);
                    acc1 = fmaf(i2, w1.z, acc1); acc1 = fmaf(i3, w1.w, acc1);
                    acc2 = fmaf(i0, w2.x, acc2); acc2 = fmaf(i1, w2.y, acc2);
                    acc2 = fmaf(i2, w2.z, acc2); acc2 = fmaf(i3, w2.w, acc2);
                    acc3 = fmaf(i0, w3.x, acc3); acc3 = fmaf(i1, w3.y, acc3);
                    acc3 = fmaf(i2, w3.z, acc3); acc3 = fmaf(i3, w3.w, acc3);
                }
                #pragma unroll
                for (int c4 = 0; c4 < Cn / 4; c4++) {
                    float4 w0 = *(const float4*)(w_ctx + (size_t)(h + 0) * Cn + c4 * 4);
                    float4 w1 = *(const float4*)(w_ctx + (size_t)(h + 1) * Cn + c4 * 4);
                    float4 w2 = *(const float4*)(w_ctx + (size_t)(h + 2) * Cn + c4 * 4);
                    float4 w3 = *(const float4*)(w_ctx + (size_t)(h + 3) * Cn + c4 * 4);
                    float i0 = cin_r[4*c4], i1 = cin_r[4*c4+1];
                    float i2 = cin_r[4*c4+2], i3 = cin_r[4*c4+3];
                    acc0 = fmaf(i0, w0.x, acc0); acc0 = fmaf(i1, w0.y, acc0);
                    acc0 = fmaf(i2, w0.z, acc0); acc0 = fmaf(i3, w0.w, acc0);
                    acc1 = fmaf(i0, w1.x, acc1); acc1 = fmaf(i1, w1.y, acc1);
                    acc1 = fmaf(i2, w1.z, acc1); acc1 = fmaf(i3, w1.w, acc1);
                    acc2 = fmaf(i0, w2.x, acc2); acc2 = fmaf(i1, w2.y, acc2);
                    acc2 = fmaf(i2, w2.z, acc2); acc2 = fmaf(i3, w2.w, acc2);
                    acc3 = fmaf(i0, w3.x, acc3); acc3 = fmaf(i1, w3.y, acc3);
                    acc3 = fmaf(i2, w3.z, acc3); acc3 = fmaf(i3, w3.w, acc3);
                }
                float4 nz = nzp[h >> 2];
                float* gd = g_drive + ((size_t)t * Hn + h) * Bn + bb;
                gd[0]      = fmaf(NZ_SCALE, nz.x, acc0);
                gd[Bn]     = fmaf(NZ_SCALE, nz.y, acc1);
                gd[2 * Bn] = fmaf(NZ_SCALE, nz.z, acc2);
                gd[3 * Bn] = fmaf(NZ_SCALE, nz.w, acc3);
            }
        }
    }

    gbar(NCTA);   // drive complete

    // ---- P2: scan ----
    float h[4], sx[4], su[4];
    #pragma unroll
    for (int jj = 0; jj < 4; jj++) {
        h[jj] = 0.f;
        sx[jj] = 1.f;
        su[jj] = (jj & 1) ? 0.15f : 0.45f;
    }

    const uint32_t hp_sm_addr = (uint32_t)__cvta_generic_to_shared(hp_sm);

    for (int step = 0; step < Tn; step++) {
        const unsigned stp1 = 16u * (unsigned)(step + 1);
        const int par = step & 1;

        // drive prefetch (DRAM; overlaps the flag wait)
        const float* gd = g_drive + ((size_t)step * Hn + jg) * Bn + b;
        float d0 = __ldcg(gd), d1 = __ldcg(gd + Bn);
        float d2 = __ldcg(gd + 2 * Bn), d3 = __ldcg(gd + 3 * Bn);

        // ---- wait: h_post rows for my k-slice ready (acquire) ----
        if (tid == 0) {
            while (ld_acq(&g_hcnt[kc32]) < stp1) { }
        }
        __syncthreads();

        // ---- phase A: stage h_post k-slice (L1-bypassing cp.async) ----
        {
            const float* src0 = g_hp[par] + (size_t)(kc * KSL) * Bn;
            #pragma unroll
            for (int i = 0; i < 8; i++) {
                int s = tid + i * 256;
                cp_async16(hp_sm_addr + s * 16, src0 + s * 4);
            }
            cp_commit();
            #pragma unroll
            for (int i = 0; i < 8; i++) {
                int s = tid + i * 256;
                cp_async16(hp_sm_addr + 32768 + s * 16, src0 + 8192 + s * 4);
            }
            cp_commit();
        }

        unsigned long long acc[4][4];
        #pragma unroll
        for (int bi = 0; bi < 4; bi++)
            #pragma unroll
            for (int jp = 0; jp < 4; jp++) acc[bi][jp] = 0ull;

        cp_wait<1>();
        __syncthreads();

        #pragma unroll 4
        for (int kl = 0; kl < 64; kl++) {
            float4 hp = *(const float4*)(hp_sm + kl * Bn + 4 * q);
            const ulonglong2* wp = (const ulonglong2*)(w_sm + kl * JSL + w * 8);
            ulonglong2 w01 = wp[0], w23 = wp[1];
            unsigned long long p0 = pack2(hp.x), p1 = pack2(hp.y);
            unsigned long long p2 = pack2(hp.z), p3 = pack2(hp.w);
            acc[0][0] = fma2(p0, w01.x, acc[0][0]); acc[0][1] = fma2(p0, w01.y, acc[0][1]);
            acc[0][2] = fma2(p0, w23.x, acc[0][2]); acc[0][3] = fma2(p0, w23.y, acc[0][3]);
            acc[1][0] = fma2(p1, w01.x, acc[1][0]); acc[1][1] = fma2(p1, w01.y, acc[1][1]);
            acc[1][2] = fma2(p1, w23.x, acc[1][2]); acc[1][3] = fma2(p1, w23.y, acc[1][3]);
            acc[2][0] = fma2(p2, w01.x, acc[2][0]); acc[2][1] = fma2(p2, w01.y, acc[2][1]);
            acc[2][2] = fma2(p2, w23.x, acc[2][2]); acc[2][3] = fma2(p2, w23.y, acc[2][3]);
            acc[3][0] = fma2(p3, w01.x, acc[3][0]); acc[3][1] = fma2(p3, w01.y, acc[3][1]);
            acc[3][2] = fma2(p3, w23.x, acc[3][2]); acc[3][3] = fma2(p3, w23.y, acc[3][3]);
        }

        cp_wait<0>();
        __syncthreads();

        #pragma unroll 4
        for (int kl = 64; kl < 128; kl++) {
            float4 hp = *(const float4*)(hp_sm + kl * Bn + 4 * q);
            const ulonglong2* wp = (const ulonglong2*)(w_sm + kl * JSL + w * 8);
            ulonglong2 w01 = wp[0], w23 = wp[1];
            unsigned long long p0 = pack2(hp.x), p1 = pack2(hp.y);
            unsigned long long p2 = pack2(hp.z), p3 = pack2(hp.w);
            acc[0][0] = fma2(p0, w01.x, acc[0][0]); acc[0][1] = fma2(p0, w01.y, acc[0][1]);
            acc[0][2] = fma2(p0, w23.x, acc[0][2]); acc[0][3] = fma2(p0, w23.y, acc[0][3]);
            acc[1][0] = fma2(p1, w01.x, acc[1][0]); acc[1][1] = fma2(p1, w01.y, acc[1][1]);
            acc[1][2] = fma2(p1, w23.x, acc[1][2]); acc[1][3] = fma2(p1, w23.y, acc[1][3]);
            acc[2][0] = fma2(p2, w01.x, acc[2][0]); acc[2][1] = fma2(p2, w01.y, acc[2][1]);
            acc[2][2] = fma2(p2, w23.x, acc[2][2]); acc[2][3] = fma2(p2, w23.y, acc[2][3]);
            acc[3][0] = fma2(p3, w01.x, acc[3][0]); acc[3][1] = fma2(p3, w01.y, acc[3][1]);
            acc[3][2] = fma2(p3, w23.x, acc[3][2]); acc[3][3] = fma2(p3, w23.y, acc[3][3]);
        }

        // write partials [kc][j][b]
        float* gpart = g_part[par];
        #pragma unroll
        for (int jp = 0; jp < 4; jp++) {
            float l0, h0v, l1, h1v, l2, h2v, l3, h3v;
            unpack2(acc[0][jp], l0, h0v);
            unpack2(acc[1][jp], l1, h1v);
            unpack2(acc[2][jp], l2, h2v);
            unpack2(acc[3][jp], l3, h3v);
            int j = jc * JSL + w * 8 + 2 * jp;
            *(float4*)(gpart + ((size_t)kc * Hn + j) * Bn + 4 * q) =
                make_float4(l0, l1, l2, l3);
            *(float4*)(gpart + ((size_t)kc * Hn + j + 1) * Bn + 4 * q) =
                make_float4(h0v, h1v, h2v, h3v);
        }

        announce(&g_kcnt[kc32]);

        // ---- phase B: wait all 8 partial groups (acquire, thread 0) ----
        if (tid == 0) {
            for (;;) {
                unsigned ok = 1;
                #pragma unroll
                for (int k2 = 0; k2 < NKC; k2++)
                    ok &= (ld_acq(&g_kcnt[k2 * 32]) >= stp1) ? 1u : 0u;
                if (ok) break;
            }
        }
        __syncthreads();

        float s0 = 0.f, s1 = 0.f, s2 = 0.f, s3 = 0.f;
        #pragma unroll
        for (int k2 = 0; k2 < NKC; k2++) {
            const float* pp = gpart + ((size_t)k2 * Hn + jg) * Bn + b;
            s0 += __ldcg(pp);
            s1 += __ldcg(pp + Bn);
            s2 += __ldcg(pp + 2 * Bn);
            s3 += __ldcg(pp + 3 * Bn);
        }
        float ss[4] = {s0, s1, s2, s3};
        float dd[4] = {d0, d1, d2, d3};
        float hn[4];
        #pragma unroll
        for (int jj = 0; jj < 4; jj++) {
            float val = h[jj] * (1.f - ALPHA_N)
                      + ALPHA_N * (dd[jj] + ss[jj] + br[jj]);
            hn[jj] = fmaxf(val, 0.f);
            h[jj] = hn[jj];
        }
        *(float4*)(acts + ((size_t)b * Tn + step) * Hn + jg) =
            make_float4(hn[0], hn[1], hn[2], hn[3]);

        // STP + h_post(step+1) into the other buffer, announce
        float* hpn = g_hp[par ^ 1];
        #pragma unroll
        for (int jj = 0; jj < 4; jj++) {
            const float axv = (jj & 1) ? AX_FAST : AX_SLOW;
            const float Uv  = (jj & 1) ? 0.15f : 0.45f;
            float hh = h[jj];
            float sxo = sx[jj], suo = su[jj];
            float sxn = sxo + axv * (1.f - sxo) - DT_SEC * suo * sxo * hh;
            float sun = suo + axv * (Uv - suo) + DT_SEC * Uv * (1.f - suo) * hh;
            sxn = fminf(fmaxf(sxn, 0.f), 1.f);
            sun = fminf(fmaxf(sun, 0.f), 1.f);
            sx[jj] = sxn; su[jj] = sun;
            hpn[(jg + jj) * Bn + b] = sun * sxn * hh;
        }
        announce(&g_hcnt[hg32]);
    }

    gbar(2 * NCTA);   // scan complete

    // ---- P3: post (fused readout) ----
    {
        float* s_comb = sm + SM_COMB;
        for (int i = tid; i < NR * Hn; i += 256) s_comb[i] = g_comb[i];
        __syncthreads();

        const int wid = tid >> 5, lane = tid & 31;
        const float4* comb4 = (const float4*)s_comb;

        for (int u = c; u < (Bn * Tn) / PR_ROWS; u += NCTA) {
            #pragma unroll 1
            for (int rr = 0; rr < 4; rr++) {
                const int bt = u * PR_ROWS + wid * 4 + rr;
                const float4* a4 = (const float4*)(acts + (size_t)bt * Hn);

                float acc[NR];
                #pragma unroll
                for (int r = 0; r < NR; r++) acc[r] = 0.f;

                #pragma unroll
                for (int it = 0; it < Hn / 128; it++) {
                    float4 a = a4[it * 32 + lane];
                    #pragma unroll
                    for (int r = 0; r < NR; r++) {
                        float4 ww = comb4[r * 256 + it * 32 + lane];
                        float s = a.x * ww.x + a.y * ww.y;
                        s = fmaf(a.z, ww.z, s);
                        s = fmaf(a.w, ww.w, s);
                        acc[r] += s;
                    }
                }
                #pragma unroll
                for (int r = 0; r < NR; r++) {
                    #pragma unroll
                    for (int off = 16; off > 0; off >>= 1)
                        acc[r] += __shfl_down_sync(0xffffffffu, acc[r], off);
                }
                if (lane == 0) {
                    #pragma unroll
                    for (int r = 0; r < NOUTn; r++)
                        out0[(size_t)bt * NOUTn + r] = acc[r] + g_combb[r];
                    #pragma unroll
                    for (int r = NOUTn; r < NR; r++)
                        pout[(size_t)bt * (NCLSn * CLSOUTn) + (r - NOUTn)]
                            = acc[r] + g_combb[r];
                }
            }
        }
    }
}

// ---------------- launch ----------------
extern "C" void kernel_launch(void* const* d_in, const int* in_sizes, int n_in,
                              void* d_out, int out_size) {
    const float* stim  = (const float*)d_in[0];
    const float* ctx   = (const float*)d_in[1];
    const float* w_rec = (const float*)d_in[2];
    const float* b_rec = (const float*)d_in[3];
    const float* w_in  = (const float*)d_in[4];
    const float* w_ctx = (const float*)d_in[5];
    const float* w_out = (const float*)d_in[6];
    const float* b_out = (const float*)d_in[7];
    const float* c1_w  = (const float*)d_in[8];
    const float* c1_b  = (const float*)d_in[9];
    const float* c2_w  = (const float*)d_in[10];
    const float* c2_b  = (const float*)d_in[11];
    const float* noise = (const float*)d_in[12];

    float* out0 = (float*)d_out;                         // [B, T, 3]
    float* acts = out0 + (size_t)Bn * Tn * NOUTn;        // [B, T, H]
    float* pout = acts + (size_t)Bn * Tn * Hn;           // [B, T, 3, 8]

    static bool attr_set = false;
    if (!attr_set) {
        cudaFuncSetAttribute(mega_kernel,
                             cudaFuncAttributeMaxDynamicSharedMemorySize,
                             SMEM_BYTES);
        attr_set = true;
    }

    reset_kernel<<<1, 256>>>();
    mega_kernel<<<NCTA, 256, SMEM_BYTES>>>(
        stim, ctx, w_rec, b_rec, w_in, w_ctx, w_out, b_out,
        c1_w, c1_b, c2_w, c2_b, noise, out0, acts, pout);
}